// round 2
// baseline (speedup 1.0000x reference)
#include <cuda_runtime.h>

#define Sdim 2048
#define Bdim 2
#define Edim 1024
#define Hn   16
#define HDdim 64
#define Mrows (Sdim*Bdim)   // 4096 token rows

// Scratch (device globals: allocation-free per harness rules)
__device__ float g_Q[(size_t)Bdim*Hn*Sdim*HDdim];   // [b*H+h][s][d]
__device__ float g_K[(size_t)Bdim*Hn*Sdim*HDdim];
__device__ float g_V[(size_t)Bdim*Hn*Sdim*HDdim];
__device__ float g_ctx[(size_t)Mrows*Edim];         // [s*B+b][E]

// C[M,N] = X[M,K] @ W[N,K]^T + bias, K = N = E. 64x64 tile, 256 threads, 4x4/thread.
// DEST 0/1/2: scatter into g_Q/g_K/g_V head-major. DEST 3: read g_ctx, write plain out.
template<int DEST>
__global__ __launch_bounds__(256) void gemm_nt_bias(
        const float* __restrict__ X, const float* __restrict__ W,
        const float* __restrict__ bias, float* __restrict__ out) {
    __shared__ float As[64][17];
    __shared__ float Bs[64][17];
    const int tid = threadIdx.x;
    const int tx = tid & 15, ty = tid >> 4;
    const int m0 = blockIdx.y << 6, n0 = blockIdx.x << 6;
    const int lr = tid >> 2;          // 0..63
    const int lc = (tid & 3) << 2;    // 0,4,8,12
    const float* Xp = (DEST == 3) ? (const float*)g_ctx : X;

    float acc[4][4] = {};
    const float* xrow = Xp + (size_t)(m0 + lr) * Edim + lc;
    const float* wrow = W  + (size_t)(n0 + lr) * Edim + lc;

    for (int k0 = 0; k0 < Edim; k0 += 16) {
        float4 a = *(const float4*)(xrow + k0);
        float4 b = *(const float4*)(wrow + k0);
        As[lr][lc+0]=a.x; As[lr][lc+1]=a.y; As[lr][lc+2]=a.z; As[lr][lc+3]=a.w;
        Bs[lr][lc+0]=b.x; Bs[lr][lc+1]=b.y; Bs[lr][lc+2]=b.z; Bs[lr][lc+3]=b.w;
        __syncthreads();
#pragma unroll
        for (int kk = 0; kk < 16; kk++) {
            float av[4], bv[4];
#pragma unroll
            for (int i = 0; i < 4; i++) av[i] = As[(ty<<2)+i][kk];
#pragma unroll
            for (int j = 0; j < 4; j++) bv[j] = Bs[(tx<<2)+j][kk];
#pragma unroll
            for (int i = 0; i < 4; i++)
#pragma unroll
                for (int j = 0; j < 4; j++)
                    acc[i][j] = fmaf(av[i], bv[j], acc[i][j]);
        }
        __syncthreads();
    }

    const int nb = n0 + (tx<<2);
#pragma unroll
    for (int i = 0; i < 4; i++) {
        const int m = m0 + (ty<<2) + i;
        float4 r;
        r.x = acc[i][0] + bias[nb+0];
        r.y = acc[i][1] + bias[nb+1];
        r.z = acc[i][2] + bias[nb+2];
        r.w = acc[i][3] + bias[nb+3];
        if (DEST == 3) {
            *(float4*)(out + (size_t)m * Edim + nb) = r;
        } else {
            const int s = m >> 1, b = m & 1;        // m = s*B + b (B=2)
            const int h = nb >> 6, d = nb & 63;     // n-tile == one head
            float* dst = (DEST == 0) ? g_Q : (DEST == 1) ? g_K : g_V;
            *(float4*)(dst + ((size_t)(b*Hn + h) * Sdim + s) * HDdim + d) = r;
        }
    }
}

// Flash attention, fp32, unscaled scores (faithful to reference).
// Block = (qtile of 64 rows, one bh). 256 threads as 16x16; scores thread-tile 4x2,
// output thread-tile 4x4. BLOCK_N = 32 keys/iter.
__global__ __launch_bounds__(256) void flash_attn_kernel() {
    __shared__ float Qs[64][65];
    __shared__ float Ks[32][65];
    __shared__ float Vs[32][64];
    __shared__ float Ps[64][33];

    const int tid = threadIdx.x;
    const int tx = tid & 15, ty = tid >> 4;
    const int bh = blockIdx.y;            // b*H + h
    const int q0 = blockIdx.x << 6;

    const float* Qp = g_Q + ((size_t)bh * Sdim + q0) * HDdim;
    const float* Kp = g_K + (size_t)bh * Sdim * HDdim;
    const float* Vp = g_V + (size_t)bh * Sdim * HDdim;

    // Load Q tile 64x64 (1024 float4, 4/thread)
    for (int i = tid; i < 64*16; i += 256) {
        const int r = i >> 4, c = (i & 15) << 2;
        float4 v = *(const float4*)(Qp + r*HDdim + c);
        Qs[r][c+0]=v.x; Qs[r][c+1]=v.y; Qs[r][c+2]=v.z; Qs[r][c+3]=v.w;
    }

    float acc[4][4] = {};
    float mrow[4] = {-1e30f,-1e30f,-1e30f,-1e30f};
    float lrow[4] = {0.f,0.f,0.f,0.f};

    for (int kt = 0; kt < Sdim/32; kt++) {
        // Load K and V tiles 32x64 (512 float4 each, 2/thread each)
        for (int i = tid; i < 32*16; i += 256) {
            const int r = i >> 4, c = (i & 15) << 2;
            float4 kv = *(const float4*)(Kp + (size_t)(kt*32 + r)*HDdim + c);
            Ks[r][c+0]=kv.x; Ks[r][c+1]=kv.y; Ks[r][c+2]=kv.z; Ks[r][c+3]=kv.w;
            float4 vv = *(const float4*)(Vp + (size_t)(kt*32 + r)*HDdim + c);
            Vs[r][c+0]=vv.x; Vs[r][c+1]=vv.y; Vs[r][c+2]=vv.z; Vs[r][c+3]=vv.w;
        }
        __syncthreads();

        // S = Q @ K^T  (64x32), thread owns rows ty*4+i, cols tx*2+j
        float s[4][2] = {};
#pragma unroll
        for (int kk = 0; kk < 64; kk++) {
            float av[4], bv[2];
#pragma unroll
            for (int i = 0; i < 4; i++) av[i] = Qs[(ty<<2)+i][kk];
#pragma unroll
            for (int j = 0; j < 2; j++) bv[j] = Ks[(tx<<1)+j][kk];
#pragma unroll
            for (int i = 0; i < 4; i++) {
                s[i][0] = fmaf(av[i], bv[0], s[i][0]);
                s[i][1] = fmaf(av[i], bv[1], s[i][1]);
            }
        }

        // Online softmax (row groups = 16 consecutive lanes, same ty)
#pragma unroll
        for (int i = 0; i < 4; i++) {
            float mx = fmaxf(s[i][0], s[i][1]);
#pragma unroll
            for (int off = 8; off >= 1; off >>= 1)
                mx = fmaxf(mx, __shfl_xor_sync(0xffffffffu, mx, off, 16));
            const float mnew = fmaxf(mrow[i], mx);
            const float p0 = __expf(s[i][0] - mnew);
            const float p1 = __expf(s[i][1] - mnew);
            float rs = p0 + p1;
#pragma unroll
            for (int off = 8; off >= 1; off >>= 1)
                rs += __shfl_xor_sync(0xffffffffu, rs, off, 16);
            const float alpha = __expf(mrow[i] - mnew);
            lrow[i] = lrow[i] * alpha + rs;
            mrow[i] = mnew;
#pragma unroll
            for (int j = 0; j < 4; j++) acc[i][j] *= alpha;
            Ps[(ty<<2)+i][(tx<<1)+0] = p0;
            Ps[(ty<<2)+i][(tx<<1)+1] = p1;
        }
        __syncthreads();

        // O += P @ V  (64x64), thread owns rows ty*4+i, cols tx*4..+3
#pragma unroll
        for (int c = 0; c < 32; c++) {
            const float4 v = *(const float4*)&Vs[c][tx<<2];
#pragma unroll
            for (int i = 0; i < 4; i++) {
                const float p = Ps[(ty<<2)+i][c];
                acc[i][0] = fmaf(p, v.x, acc[i][0]);
                acc[i][1] = fmaf(p, v.y, acc[i][1]);
                acc[i][2] = fmaf(p, v.z, acc[i][2]);
                acc[i][3] = fmaf(p, v.w, acc[i][3]);
            }
        }
        __syncthreads();
    }

    // Epilogue: normalize and write to ctx [s*B+b][h*HD+d]
    const int b = bh >> 4, h = bh & 15;
#pragma unroll
    for (int i = 0; i < 4; i++) {
        const float inv = 1.0f / lrow[i];
        const int sg = q0 + (ty<<2) + i;
        float4 r;
        r.x = acc[i][0]*inv; r.y = acc[i][1]*inv;
        r.z = acc[i][2]*inv; r.w = acc[i][3]*inv;
        *(float4*)(g_ctx + ((size_t)sg * Bdim + b) * Edim + h*HDdim + (tx<<2)) = r;
    }
}

extern "C" void kernel_launch(void* const* d_in, const int* in_sizes, int n_in,
                              void* d_out, int out_size) {
    const float* query = (const float*)d_in[0];
    const float* key_  = (const float*)d_in[1];
    const float* value = (const float*)d_in[2];
    const float* Wq = (const float*)d_in[3];
    const float* bq = (const float*)d_in[4];
    const float* Wk = (const float*)d_in[5];
    const float* bk = (const float*)d_in[6];
    const float* Wv = (const float*)d_in[7];
    const float* bv = (const float*)d_in[8];
    const float* Wo = (const float*)d_in[9];
    const float* bo = (const float*)d_in[10];
    float* out = (float*)d_out;

    dim3 gproj(Edim/64, Mrows/64);   // 16 x 64
    gemm_nt_bias<0><<<gproj, 256>>>(query, Wq, bq, nullptr);
    gemm_nt_bias<1><<<gproj, 256>>>(key_,  Wk, bk, nullptr);
    gemm_nt_bias<2><<<gproj, 256>>>(value, Wv, bv, nullptr);

    flash_attn_kernel<<<dim3(Sdim/64, Bdim*Hn), 256>>>();

    gemm_nt_bias<3><<<gproj, 256>>>(nullptr, Wo, bo, out);
}

// round 3
// speedup vs baseline: 1.2389x; 1.2389x over previous
#include <cuda_runtime.h>

#define Sdim 2048
#define Bdim 2
#define Edim 1024
#define Hn   16
#define HDdim 64
#define Mrows (Sdim*Bdim)   // 4096 token rows

// Scratch (device globals: allocation-free per harness rules)
__device__ float g_Q[(size_t)Bdim*Hn*Sdim*HDdim];   // [b*H+h][s][d]
__device__ float g_K[(size_t)Bdim*Hn*Sdim*HDdim];
__device__ float g_V[(size_t)Bdim*Hn*Sdim*HDdim];
__device__ float g_ctx[(size_t)Mrows*Edim];         // [s*B+b][E]

// C[M,N] = X[M,K] @ W[N,K]^T + bias.  128x128 tile, 256 threads, 8x8/thread.
// Smem stored k-major so operand fetches are LDS.128 (4 LDS.128 : 64 FMA per k-step).
// DEST 0/1/2: scatter into g_Q/g_K/g_V head-major. DEST 3: read g_ctx, write out.
template<int DEST>
__global__ __launch_bounds__(256, 2) void gemm_nt_bias(
        const float* __restrict__ X, const float* __restrict__ W,
        const float* __restrict__ bias, float* __restrict__ out) {
    __shared__ float As[16][132];   // [k][m], pad 132 keeps stores conflict-free & rows 16B-aligned
    __shared__ float Bs[16][132];   // [k][n]
    const int tid = threadIdx.x;
    const int tx = tid & 15, ty = tid >> 4;
    const int m0 = blockIdx.y << 7, n0 = blockIdx.x << 7;
    const float* Xp = (DEST == 3) ? (const float*)g_ctx : X;

    const int lr = tid >> 2;          // 0..63
    const int lc = (tid & 3) << 2;    // 0,4,8,12
    const float* xrow = Xp + (size_t)(m0 + lr) * Edim + lc;
    const float* wrow = W  + (size_t)(n0 + lr) * Edim + lc;

    float acc[8][8] = {};

    for (int k0 = 0; k0 < Edim; k0 += 16) {
        float4 a0 = *(const float4*)(xrow + k0);
        float4 a1 = *(const float4*)(xrow + (size_t)64*Edim + k0);
        float4 b0 = *(const float4*)(wrow + k0);
        float4 b1 = *(const float4*)(wrow + (size_t)64*Edim + k0);
        __syncthreads();   // previous compute done reading smem
        As[lc+0][lr]=a0.x; As[lc+1][lr]=a0.y; As[lc+2][lr]=a0.z; As[lc+3][lr]=a0.w;
        As[lc+0][lr+64]=a1.x; As[lc+1][lr+64]=a1.y; As[lc+2][lr+64]=a1.z; As[lc+3][lr+64]=a1.w;
        Bs[lc+0][lr]=b0.x; Bs[lc+1][lr]=b0.y; Bs[lc+2][lr]=b0.z; Bs[lc+3][lr]=b0.w;
        Bs[lc+0][lr+64]=b1.x; Bs[lc+1][lr+64]=b1.y; Bs[lc+2][lr+64]=b1.z; Bs[lc+3][lr+64]=b1.w;
        __syncthreads();
#pragma unroll
        for (int kk = 0; kk < 16; kk++) {
            float av[8], bv[8];
            *(float4*)(av)   = *(const float4*)&As[kk][ty<<3];
            *(float4*)(av+4) = *(const float4*)&As[kk][(ty<<3)+4];
            *(float4*)(bv)   = *(const float4*)&Bs[kk][tx<<3];
            *(float4*)(bv+4) = *(const float4*)&Bs[kk][(tx<<3)+4];
#pragma unroll
            for (int i = 0; i < 8; i++)
#pragma unroll
                for (int j = 0; j < 8; j++)
                    acc[i][j] = fmaf(av[i], bv[j], acc[i][j]);
        }
    }

#pragma unroll
    for (int i = 0; i < 8; i++) {
        const int m = m0 + (ty<<3) + i;
#pragma unroll
        for (int jv = 0; jv < 2; jv++) {
            const int nb = n0 + (tx<<3) + (jv<<2);
            const float4 bb = *(const float4*)(bias + nb);
            float4 r;
            r.x = acc[i][jv*4+0] + bb.x;
            r.y = acc[i][jv*4+1] + bb.y;
            r.z = acc[i][jv*4+2] + bb.z;
            r.w = acc[i][jv*4+3] + bb.w;
            if (DEST == 3) {
                *(float4*)(out + (size_t)m * Edim + nb) = r;
            } else {
                const int s = m >> 1, b = m & 1;        // m = s*B + b (B=2)
                const int h = nb >> 6, d = nb & 63;     // 8-aligned, never straddles a head
                float* dst = (DEST == 0) ? g_Q : (DEST == 1) ? g_K : g_V;
                *(float4*)(dst + ((size_t)(b*Hn + h) * Sdim + s) * HDdim + d) = r;
            }
        }
    }
}

// Flash attention, fp32, unscaled scores (faithful to reference).
// BLOCK_M=128 q rows, BLOCK_N=64 keys. 256 threads as 16x16.
// Scores thread-tile 8x4; output thread-tile 8x4. Q/K/P k-major in smem so
// inner loops are 3 LDS.128 : 32 FMA. 100KB dynamic smem.
#define FL_SMEM_BYTES (size_t)((64*132 + 64*68 + 64*68 + 64*132) * 4)

__global__ __launch_bounds__(256, 2) void flash_attn_kernel() {
    extern __shared__ float sm[];
    float (*Qs)[132] = (float(*)[132])(sm);                       // [d=64][m=128(+4)]
    float (*Ks)[68]  = (float(*)[68]) (sm + 64*132);              // [d=64][n=64(+4)]
    float (*Vs)[68]  = (float(*)[68]) (sm + 64*132 + 64*68);      // [c=64][d=64(+4)]
    float (*Ps)[132] = (float(*)[132])(sm + 64*132 + 2*64*68);    // [c=64][m=128(+4)]

    const int tid = threadIdx.x;
    const int tx = tid & 15, ty = tid >> 4;
    const int bh = blockIdx.y;            // b*H + h
    const int q0 = blockIdx.x << 7;

    const float* Qp = g_Q + ((size_t)bh * Sdim + q0) * HDdim;
    const float* Kp = g_K + (size_t)bh * Sdim * HDdim;
    const float* Vp = g_V + (size_t)bh * Sdim * HDdim;

    // Load Q tile 128x64 -> Qs[d][m] (transposed)
    for (int i = tid; i < 128*16; i += 256) {
        const int m = i >> 4, d = (i & 15) << 2;
        float4 v = *(const float4*)(Qp + m*HDdim + d);
        Qs[d+0][m]=v.x; Qs[d+1][m]=v.y; Qs[d+2][m]=v.z; Qs[d+3][m]=v.w;
    }

    float acc[8][4] = {};
    float mrow[8], lrow[8];
#pragma unroll
    for (int i = 0; i < 8; i++) { mrow[i] = -1e30f; lrow[i] = 0.f; }

    for (int kt = 0; kt < Sdim/64; kt++) {
        const float* Kt = Kp + (size_t)(kt*64)*HDdim;
        const float* Vt = Vp + (size_t)(kt*64)*HDdim;
        // Stage loads into regs (4 float4 K + 4 float4 V per thread)
        float4 kr[4], vr[4];
#pragma unroll
        for (int u = 0; u < 4; u++) {
            const int i = tid + u*256;
            const int n = i >> 4, d = (i & 15) << 2;
            kr[u] = *(const float4*)(Kt + n*HDdim + d);
            vr[u] = *(const float4*)(Vt + n*HDdim + d);
        }
        __syncthreads();   // previous PV done reading Ks/Vs
#pragma unroll
        for (int u = 0; u < 4; u++) {
            const int i = tid + u*256;
            const int n = i >> 4, d = (i & 15) << 2;
            Ks[d+0][n]=kr[u].x; Ks[d+1][n]=kr[u].y; Ks[d+2][n]=kr[u].z; Ks[d+3][n]=kr[u].w;
            *(float4*)&Vs[n][d] = vr[u];
        }
        __syncthreads();

        // S = Q @ K^T  (128x64): thread rows ty*8+i, cols tx*4+j
        float s[8][4] = {};
#pragma unroll
        for (int kk = 0; kk < 64; kk++) {
            float av[8], bv[4];
            *(float4*)(av)   = *(const float4*)&Qs[kk][ty<<3];
            *(float4*)(av+4) = *(const float4*)&Qs[kk][(ty<<3)+4];
            *(float4*)(bv)   = *(const float4*)&Ks[kk][tx<<2];
#pragma unroll
            for (int i = 0; i < 8; i++)
#pragma unroll
                for (int j = 0; j < 4; j++)
                    s[i][j] = fmaf(av[i], bv[j], s[i][j]);
        }

        // Online softmax; rows reduce across 16-lane groups (same ty)
#pragma unroll
        for (int i = 0; i < 8; i++) {
            float mx = fmaxf(fmaxf(s[i][0], s[i][1]), fmaxf(s[i][2], s[i][3]));
#pragma unroll
            for (int off = 8; off >= 1; off >>= 1)
                mx = fmaxf(mx, __shfl_xor_sync(0xffffffffu, mx, off, 16));
            const float mnew = fmaxf(mrow[i], mx);
            float p[4], rs = 0.f;
#pragma unroll
            for (int j = 0; j < 4; j++) { p[j] = __expf(s[i][j] - mnew); rs += p[j]; }
#pragma unroll
            for (int off = 8; off >= 1; off >>= 1)
                rs += __shfl_xor_sync(0xffffffffu, rs, off, 16);
            const float alpha = __expf(mrow[i] - mnew);
            lrow[i] = lrow[i] * alpha + rs;
            mrow[i] = mnew;
#pragma unroll
            for (int j = 0; j < 4; j++) acc[i][j] *= alpha;
            const int mloc = (ty<<3) + i;
#pragma unroll
            for (int j = 0; j < 4; j++) Ps[(tx<<2)+j][mloc] = p[j];
        }
        __syncthreads();

        // O += P @ V  (128x64): per c, 2 LDS.128 (P rows) + 1 LDS.128 (V cols)
#pragma unroll 4
        for (int c = 0; c < 64; c++) {
            float pv[8];
            *(float4*)(pv)   = *(const float4*)&Ps[c][ty<<3];
            *(float4*)(pv+4) = *(const float4*)&Ps[c][(ty<<3)+4];
            const float4 vv = *(const float4*)&Vs[c][tx<<2];
#pragma unroll
            for (int i = 0; i < 8; i++) {
                acc[i][0] = fmaf(pv[i], vv.x, acc[i][0]);
                acc[i][1] = fmaf(pv[i], vv.y, acc[i][1]);
                acc[i][2] = fmaf(pv[i], vv.z, acc[i][2]);
                acc[i][3] = fmaf(pv[i], vv.w, acc[i][3]);
            }
        }
    }

    // Epilogue: normalize and write to ctx [s*B+b][h*HD+d]
    const int b = bh >> 4, h = bh & 15;
#pragma unroll
    for (int i = 0; i < 8; i++) {
        const float inv = 1.0f / lrow[i];
        const int sg = q0 + (ty<<3) + i;
        float4 r;
        r.x = acc[i][0]*inv; r.y = acc[i][1]*inv;
        r.z = acc[i][2]*inv; r.w = acc[i][3]*inv;
        *(float4*)(g_ctx + ((size_t)sg * Bdim + b) * Edim + h*HDdim + (tx<<2)) = r;
    }
}

extern "C" void kernel_launch(void* const* d_in, const int* in_sizes, int n_in,
                              void* d_out, int out_size) {
    const float* query = (const float*)d_in[0];
    const float* key_  = (const float*)d_in[1];
    const float* value = (const float*)d_in[2];
    const float* Wq = (const float*)d_in[3];
    const float* bq = (const float*)d_in[4];
    const float* Wk = (const float*)d_in[5];
    const float* bk = (const float*)d_in[6];
    const float* Wv = (const float*)d_in[7];
    const float* bv = (const float*)d_in[8];
    const float* Wo = (const float*)d_in[9];
    const float* bo = (const float*)d_in[10];
    float* out = (float*)d_out;

    static bool attr_set = false;
    if (!attr_set) {
        cudaFuncSetAttribute(flash_attn_kernel,
                             cudaFuncAttributeMaxDynamicSharedMemorySize,
                             (int)FL_SMEM_BYTES);
        attr_set = true;
    }

    dim3 gproj(Edim/128, Mrows/128);   // 8 x 32
    gemm_nt_bias<0><<<gproj, 256>>>(query, Wq, bq, nullptr);
    gemm_nt_bias<1><<<gproj, 256>>>(key_,  Wk, bk, nullptr);
    gemm_nt_bias<2><<<gproj, 256>>>(value, Wv, bv, nullptr);

    flash_attn_kernel<<<dim3(Sdim/128, Bdim*Hn), 256, FL_SMEM_BYTES>>>();

    gemm_nt_bias<3><<<gproj, 256>>>(nullptr, Wo, bo, out);
}

// round 5
// speedup vs baseline: 1.6447x; 1.3276x over previous
#include <cuda_runtime.h>
#include <cuda_bf16.h>

#define Sdim 2048
#define Bdim 2
#define Edim 1024
#define Hn   16
#define HDdim 64
#define Mrows (Sdim*Bdim)   // 4096 token rows

// ---------------- scratch (device globals: allocation-free) ----------------
__device__ float g_Q[(size_t)Bdim*Hn*Sdim*HDdim];   // [b*H+h][s][d]
__device__ float g_K[(size_t)Bdim*Hn*Sdim*HDdim];
__device__ float g_V[(size_t)Bdim*Hn*Sdim*HDdim];
__device__ float g_ctx[(size_t)Mrows*Edim];         // [s*B+b][E]

// bf16 split scratch (reused across the 4 GEMMs; stream-serialized)
__device__ __align__(16) __nv_bfloat16 g_ah[(size_t)Mrows*Edim];
__device__ __align__(16) __nv_bfloat16 g_al[(size_t)Mrows*Edim];
__device__ __align__(16) __nv_bfloat16 g_bh[(size_t)Edim*Edim];
__device__ __align__(16) __nv_bfloat16 g_bl[(size_t)Edim*Edim];

// ---------------- split fp32 -> (hi, lo) bf16 ----------------
__device__ __forceinline__ void split1(float x, __nv_bfloat16& h, __nv_bfloat16& l) {
    h = __float2bfloat16(x);
    l = __float2bfloat16(x - __bfloat162float(h));
}
template<int DST>
__global__ __launch_bounds__(256) void split_kernel(const float* __restrict__ xin, int n) {
    const float* x = xin ? xin : (const float*)g_ctx;
    __nv_bfloat16* hi = (DST == 0) ? g_ah : g_bh;
    __nv_bfloat16* lo = (DST == 0) ? g_al : g_bl;
    int i = (blockIdx.x * blockDim.x + threadIdx.x) * 4;
    if (i < n) {
        float4 v = *(const float4*)(x + i);
        __nv_bfloat16 h0,h1,h2,h3,l0,l1,l2,l3;
        split1(v.x,h0,l0); split1(v.y,h1,l1); split1(v.z,h2,l2); split1(v.w,h3,l3);
        __nv_bfloat162* ph = (__nv_bfloat162*)(hi + i);
        ph[0] = __halves2bfloat162(h0,h1); ph[1] = __halves2bfloat162(h2,h3);
        __nv_bfloat162* pl = (__nv_bfloat162*)(lo + i);
        pl[0] = __halves2bfloat162(l0,l1); pl[1] = __halves2bfloat162(l2,l3);
    }
}

// ---------------- mma.sync helpers ----------------
__device__ __forceinline__ void ldmat_x4(unsigned& r0, unsigned& r1, unsigned& r2,
                                         unsigned& r3, unsigned addr) {
    asm volatile("ldmatrix.sync.aligned.m8n8.x4.shared.b16 {%0,%1,%2,%3}, [%4];"
                 : "=r"(r0), "=r"(r1), "=r"(r2), "=r"(r3) : "r"(addr));
}
__device__ __forceinline__ void ldmat_x2(unsigned& r0, unsigned& r1, unsigned addr) {
    asm volatile("ldmatrix.sync.aligned.m8n8.x2.shared.b16 {%0,%1}, [%2];"
                 : "=r"(r0), "=r"(r1) : "r"(addr));
}
__device__ __forceinline__ void mma_bf16(float* c, const unsigned* a, const unsigned* b) {
    asm volatile(
        "mma.sync.aligned.m16n8k16.row.col.f32.bf16.bf16.f32 "
        "{%0,%1,%2,%3}, {%4,%5,%6,%7}, {%8,%9}, {%0,%1,%2,%3};"
        : "+f"(c[0]), "+f"(c[1]), "+f"(c[2]), "+f"(c[3])
        : "r"(a[0]), "r"(a[1]), "r"(a[2]), "r"(a[3]), "r"(b[0]), "r"(b[1]));
}
__device__ __forceinline__ void cp_async16(unsigned saddr, const void* gaddr) {
    asm volatile("cp.async.cg.shared.global [%0], [%1], 16;" :: "r"(saddr), "l"(gaddr));
}

// ---------------- tensor-core GEMM: C[4096,1024] = A @ B^T + bias ----------------
// A = g_ah + g_al, B = g_bh + g_bl; D = Ah*Bh + Ah*Bl + Al*Bh (fp32 reg accum).
// 128x128 CTA tile, 8 warps (2m x 4n), warp tile 64x32, K-block 32, dbl-buffered cp.async.
#define PITCH 40                        // bf16 elems per smem row (80 B)
#define KBLK  32
#define MAT_BYTES (128*PITCH*2)         // 10240
#define STAGE_BYTES (4*MAT_BYTES)       // 40960 (Ah, Al, Bh, Bl)
#define GEMM_SMEM (2*STAGE_BYTES)       // 81920
#define NKB (Edim/KBLK)                 // 32

template<int DEST>
__global__ __launch_bounds__(256) void gemm_tc(const float* __restrict__ bias,
                                               float* __restrict__ out) {
    extern __shared__ char smc[];
    const unsigned sbase = (unsigned)__cvta_generic_to_shared(smc);
    const int tid = threadIdx.x, lane = tid & 31, wid = tid >> 5;
    const int m0 = blockIdx.y << 7, n0 = blockIdx.x << 7;
    const int wm = (wid & 1) << 6;      // warp m offset (0/64)
    const int wn = (wid >> 1) << 5;     // warp n offset (0/32/64/96)

    // cp.async geometry: 2048 16B-chunks per stage, 8 per thread
    unsigned soff[8]; const __nv_bfloat16* gp[8];
#pragma unroll
    for (int u = 0; u < 8; u++) {
        const int i = u*256 + tid;
        const int mat = i >> 9;             // 0=Ah 1=Al 2=Bh 3=Bl
        const int row = (i >> 2) & 127, c4 = i & 3;
        soff[u] = mat*MAT_BYTES + row*(PITCH*2) + c4*16;
        const __nv_bfloat16* src = (mat==0) ? g_ah : (mat==1) ? g_al
                                  : (mat==2) ? g_bh : g_bl;
        const size_t r = (mat < 2) ? (size_t)(m0 + row) : (size_t)(n0 + row);
        gp[u] = src + r*Edim + c4*8;
    }
    auto load_stage = [&](int kb, int st) {
        const unsigned sb = sbase + st*STAGE_BYTES;
#pragma unroll
        for (int u = 0; u < 8; u++) cp_async16(sb + soff[u], gp[u] + kb*KBLK);
        asm volatile("cp.async.commit_group;");
    };

    float c[4][4][4] = {};   // [mf][nf][4]

    load_stage(0, 0);

    for (int kb = 0; kb < NKB; kb++) {
        const int st = kb & 1;
        if (kb + 1 < NKB) {
            load_stage(kb + 1, st ^ 1);
            asm volatile("cp.async.wait_group 1;");
        } else {
            asm volatile("cp.async.wait_group 0;");
        }
        __syncthreads();

        const unsigned sAh = sbase + st*STAGE_BYTES;
        const unsigned sAl = sAh + MAT_BYTES;
        const unsigned sBh = sAh + 2*MAT_BYTES;
        const unsigned sBl = sAh + 3*MAT_BYTES;
        const int arow = wm + (lane & 15);
        const int akof = (lane >> 4) << 3;
        const int brow = wn + (lane & 7);
        const int bkof = ((lane >> 3) & 1) << 3;

#pragma unroll
        for (int ks = 0; ks < 2; ks++) {
            const int k0 = ks << 4;
            unsigned ah[4][4], al[4][4], b[4][2];
#pragma unroll
            for (int mf = 0; mf < 4; mf++) {
                const unsigned off = (unsigned)(arow + mf*16)*(PITCH*2) + (k0 + akof)*2;
                ldmat_x4(ah[mf][0], ah[mf][1], ah[mf][2], ah[mf][3], sAh + off);
                ldmat_x4(al[mf][0], al[mf][1], al[mf][2], al[mf][3], sAl + off);
            }
#pragma unroll
            for (int nf = 0; nf < 4; nf++) {
                const unsigned off = (unsigned)(brow + nf*8)*(PITCH*2) + (k0 + bkof)*2;
                ldmat_x2(b[nf][0], b[nf][1], sBh + off);
            }
#pragma unroll
            for (int mf = 0; mf < 4; mf++)
#pragma unroll
                for (int nf = 0; nf < 4; nf++) {
                    mma_bf16(c[mf][nf], ah[mf], b[nf]);
                    mma_bf16(c[mf][nf], al[mf], b[nf]);
                }
#pragma unroll
            for (int nf = 0; nf < 4; nf++) {
                const unsigned off = (unsigned)(brow + nf*8)*(PITCH*2) + (k0 + bkof)*2;
                ldmat_x2(b[nf][0], b[nf][1], sBl + off);
            }
#pragma unroll
            for (int mf = 0; mf < 4; mf++)
#pragma unroll
                for (int nf = 0; nf < 4; nf++)
                    mma_bf16(c[mf][nf], ah[mf], b[nf]);
        }
        __syncthreads();
    }

    // epilogue: bias + scatter from fragments (float2 stores)
    const int g = lane >> 2, tig = lane & 3;
#pragma unroll
    for (int mf = 0; mf < 4; mf++) {
#pragma unroll
        for (int nf = 0; nf < 4; nf++) {
            const int col = n0 + wn + nf*8 + tig*2;
            const float2 bb = *(const float2*)(bias + col);
#pragma unroll
            for (int half = 0; half < 2; half++) {
                const int m = m0 + wm + mf*16 + g + half*8;
                float2 o;
                o.x = c[mf][nf][half*2+0] + bb.x;
                o.y = c[mf][nf][half*2+1] + bb.y;
                if (DEST == 3) {
                    *(float2*)(out + (size_t)m * Edim + col) = o;
                } else {
                    const int s = m >> 1, b2 = m & 1;   // m = s*B + b
                    const int h = col >> 6, d2 = col & 63;
                    float* dst = (DEST == 0) ? g_Q : (DEST == 1) ? g_K : g_V;
                    *(float2*)(dst + ((size_t)(b2*Hn + h) * Sdim + s) * HDdim + d2) = o;
                }
            }
        }
    }
}

// ---------------- flash attention (fp32 SIMT, unchanged) ----------------
#define FL_SMEM_BYTES (size_t)((64*132 + 64*68 + 64*68 + 64*132) * 4)

__global__ __launch_bounds__(256, 2) void flash_attn_kernel() {
    extern __shared__ float sm[];
    float (*Qs)[132] = (float(*)[132])(sm);
    float (*Ks)[68]  = (float(*)[68]) (sm + 64*132);
    float (*Vs)[68]  = (float(*)[68]) (sm + 64*132 + 64*68);
    float (*Ps)[132] = (float(*)[132])(sm + 64*132 + 2*64*68);

    const int tid = threadIdx.x;
    const int tx = tid & 15, ty = tid >> 4;
    const int bh = blockIdx.y;
    const int q0 = blockIdx.x << 7;

    const float* Qp = g_Q + ((size_t)bh * Sdim + q0) * HDdim;
    const float* Kp = g_K + (size_t)bh * Sdim * HDdim;
    const float* Vp = g_V + (size_t)bh * Sdim * HDdim;

    for (int i = tid; i < 128*16; i += 256) {
        const int m = i >> 4, d = (i & 15) << 2;
        float4 v = *(const float4*)(Qp + m*HDdim + d);
        Qs[d+0][m]=v.x; Qs[d+1][m]=v.y; Qs[d+2][m]=v.z; Qs[d+3][m]=v.w;
    }

    float acc[8][4] = {};
    float mrow[8], lrow[8];
#pragma unroll
    for (int i = 0; i < 8; i++) { mrow[i] = -1e30f; lrow[i] = 0.f; }

    for (int kt = 0; kt < Sdim/64; kt++) {
        const float* Kt = Kp + (size_t)(kt*64)*HDdim;
        const float* Vt = Vp + (size_t)(kt*64)*HDdim;
        float4 kr[4], vr[4];
#pragma unroll
        for (int u = 0; u < 4; u++) {
            const int i = tid + u*256;
            const int n = i >> 4, d = (i & 15) << 2;
            kr[u] = *(const float4*)(Kt + n*HDdim + d);
            vr[u] = *(const float4*)(Vt + n*HDdim + d);
        }
        __syncthreads();
#pragma unroll
        for (int u = 0; u < 4; u++) {
            const int i = tid + u*256;
            const int n = i >> 4, d = (i & 15) << 2;
            Ks[d+0][n]=kr[u].x; Ks[d+1][n]=kr[u].y; Ks[d+2][n]=kr[u].z; Ks[d+3][n]=kr[u].w;
            *(float4*)&Vs[n][d] = vr[u];
        }
        __syncthreads();

        float s[8][4] = {};
#pragma unroll
        for (int kk = 0; kk < 64; kk++) {
            float av[8], bv[4];
            *(float4*)(av)   = *(const float4*)&Qs[kk][ty<<3];
            *(float4*)(av+4) = *(const float4*)&Qs[kk][(ty<<3)+4];
            *(float4*)(bv)   = *(const float4*)&Ks[kk][tx<<2];
#pragma unroll
            for (int i = 0; i < 8; i++)
#pragma unroll
                for (int j = 0; j < 4; j++)
                    s[i][j] = fmaf(av[i], bv[j], s[i][j]);
        }

#pragma unroll
        for (int i = 0; i < 8; i++) {
            float mx = fmaxf(fmaxf(s[i][0], s[i][1]), fmaxf(s[i][2], s[i][3]));
#pragma unroll
            for (int off = 8; off >= 1; off >>= 1)
                mx = fmaxf(mx, __shfl_xor_sync(0xffffffffu, mx, off, 16));
            const float mnew = fmaxf(mrow[i], mx);
            float p[4], rs = 0.f;
#pragma unroll
            for (int j = 0; j < 4; j++) { p[j] = __expf(s[i][j] - mnew); rs += p[j]; }
#pragma unroll
            for (int off = 8; off >= 1; off >>= 1)
                rs += __shfl_xor_sync(0xffffffffu, rs, off, 16);
            const float alpha = __expf(mrow[i] - mnew);
            lrow[i] = lrow[i] * alpha + rs;
            mrow[i] = mnew;
#pragma unroll
            for (int j = 0; j < 4; j++) acc[i][j] *= alpha;
            const int mloc = (ty<<3) + i;
#pragma unroll
            for (int j = 0; j < 4; j++) Ps[(tx<<2)+j][mloc] = p[j];
        }
        __syncthreads();

#pragma unroll 4
        for (int c = 0; c < 64; c++) {
            float pv[8];
            *(float4*)(pv)   = *(const float4*)&Ps[c][ty<<3];
            *(float4*)(pv+4) = *(const float4*)&Ps[c][(ty<<3)+4];
            const float4 vv = *(const float4*)&Vs[c][tx<<2];
#pragma unroll
            for (int i = 0; i < 8; i++) {
                acc[i][0] = fmaf(pv[i], vv.x, acc[i][0]);
                acc[i][1] = fmaf(pv[i], vv.y, acc[i][1]);
                acc[i][2] = fmaf(pv[i], vv.z, acc[i][2]);
                acc[i][3] = fmaf(pv[i], vv.w, acc[i][3]);
            }
        }
    }

    const int b = bh >> 4, h = bh & 15;
#pragma unroll
    for (int i = 0; i < 8; i++) {
        const float inv = 1.0f / lrow[i];
        const int sg = q0 + (ty<<3) + i;
        float4 r;
        r.x = acc[i][0]*inv; r.y = acc[i][1]*inv;
        r.z = acc[i][2]*inv; r.w = acc[i][3]*inv;
        *(float4*)(g_ctx + ((size_t)sg * Bdim + b) * Edim + h*HDdim + (tx<<2)) = r;
    }
}

// ---------------- launch ----------------
extern "C" void kernel_launch(void* const* d_in, const int* in_sizes, int n_in,
                              void* d_out, int out_size) {
    const float* query = (const float*)d_in[0];
    const float* key_  = (const float*)d_in[1];
    const float* value = (const float*)d_in[2];
    const float* Wq = (const float*)d_in[3];
    const float* bq = (const float*)d_in[4];
    const float* Wk = (const float*)d_in[5];
    const float* bk = (const float*)d_in[6];
    const float* Wv = (const float*)d_in[7];
    const float* bv = (const float*)d_in[8];
    const float* Wo = (const float*)d_in[9];
    const float* bo = (const float*)d_in[10];
    float* out = (float*)d_out;

    static bool attr_set = false;
    if (!attr_set) {
        cudaFuncSetAttribute(flash_attn_kernel,
                             cudaFuncAttributeMaxDynamicSharedMemorySize, (int)FL_SMEM_BYTES);
        cudaFuncSetAttribute(gemm_tc<0>, cudaFuncAttributeMaxDynamicSharedMemorySize, GEMM_SMEM);
        cudaFuncSetAttribute(gemm_tc<1>, cudaFuncAttributeMaxDynamicSharedMemorySize, GEMM_SMEM);
        cudaFuncSetAttribute(gemm_tc<2>, cudaFuncAttributeMaxDynamicSharedMemorySize, GEMM_SMEM);
        cudaFuncSetAttribute(gemm_tc<3>, cudaFuncAttributeMaxDynamicSharedMemorySize, GEMM_SMEM);
        attr_set = true;
    }

    const int NA = Mrows * Edim;   // 4M
    const int NB = Edim * Edim;    // 1M
    const dim3 ggemm(Edim/128, Mrows/128);   // 8 x 32

    split_kernel<0><<<NA/1024, 256>>>(query, NA);
    split_kernel<1><<<NB/1024, 256>>>(Wq, NB);
    gemm_tc<0><<<ggemm, 256, GEMM_SMEM>>>(bq, nullptr);

    split_kernel<0><<<NA/1024, 256>>>(key_, NA);
    split_kernel<1><<<NB/1024, 256>>>(Wk, NB);
    gemm_tc<1><<<ggemm, 256, GEMM_SMEM>>>(bk, nullptr);

    split_kernel<0><<<NA/1024, 256>>>(value, NA);
    split_kernel<1><<<NB/1024, 256>>>(Wv, NB);
    gemm_tc<2><<<ggemm, 256, GEMM_SMEM>>>(bv, nullptr);

    flash_attn_kernel<<<dim3(Sdim/128, Bdim*Hn), 256, FL_SMEM_BYTES>>>();

    split_kernel<0><<<NA/1024, 256>>>(nullptr, NA);   // ctx
    split_kernel<1><<<NB/1024, 256>>>(Wo, NB);
    gemm_tc<3><<<ggemm, 256, GEMM_SMEM>>>(bo, out);
}

// round 6
// speedup vs baseline: 3.0838x; 1.8750x over previous
#include <cuda_runtime.h>
#include <cuda_bf16.h>
#include <cuda_fp16.h>

#define Sdim 2048
#define Bdim 2
#define Edim 1024
#define Hn   16
#define HDdim 64
#define Mrows (Sdim*Bdim)   // 4096 token rows

// ---------------- scratch (device globals: allocation-free) ----------------
__device__ float g_ctx[(size_t)Mrows*Edim];         // [s*B+b][E]

// fp16 split QKV (written by projection epilogues), layout [b*H+h][s][d]
#define QKV_ELEMS ((size_t)Bdim*Hn*Sdim*HDdim)
__device__ __align__(16) __half g_Qh[QKV_ELEMS];
__device__ __align__(16) __half g_Ql[QKV_ELEMS];
__device__ __align__(16) __half g_Kh[QKV_ELEMS];
__device__ __align__(16) __half g_Kl[QKV_ELEMS];
__device__ __align__(16) __half g_Vh[QKV_ELEMS];
__device__ __align__(16) __half g_Vl[QKV_ELEMS];

// bf16 split scratch for projection GEMMs
__device__ __align__(16) __nv_bfloat16 g_ah[(size_t)Mrows*Edim];
__device__ __align__(16) __nv_bfloat16 g_al[(size_t)Mrows*Edim];
__device__ __align__(16) __nv_bfloat16 g_bh[(size_t)Edim*Edim];
__device__ __align__(16) __nv_bfloat16 g_bl[(size_t)Edim*Edim];

// ---------------- split fp32 -> (hi, lo) bf16 ----------------
__device__ __forceinline__ void split1(float x, __nv_bfloat16& h, __nv_bfloat16& l) {
    h = __float2bfloat16(x);
    l = __float2bfloat16(x - __bfloat162float(h));
}
template<int DST>
__global__ __launch_bounds__(256) void split_kernel(const float* __restrict__ xin, int n) {
    const float* x = xin ? xin : (const float*)g_ctx;
    __nv_bfloat16* hi = (DST == 0) ? g_ah : g_bh;
    __nv_bfloat16* lo = (DST == 0) ? g_al : g_bl;
    int i = (blockIdx.x * blockDim.x + threadIdx.x) * 4;
    if (i < n) {
        float4 v = *(const float4*)(x + i);
        __nv_bfloat16 h0,h1,h2,h3,l0,l1,l2,l3;
        split1(v.x,h0,l0); split1(v.y,h1,l1); split1(v.z,h2,l2); split1(v.w,h3,l3);
        __nv_bfloat162* ph = (__nv_bfloat162*)(hi + i);
        ph[0] = __halves2bfloat162(h0,h1); ph[1] = __halves2bfloat162(h2,h3);
        __nv_bfloat162* pl = (__nv_bfloat162*)(lo + i);
        pl[0] = __halves2bfloat162(l0,l1); pl[1] = __halves2bfloat162(l2,l3);
    }
}

// ---------------- mma helpers ----------------
__device__ __forceinline__ void ldmat_x4(unsigned& r0, unsigned& r1, unsigned& r2,
                                         unsigned& r3, unsigned addr) {
    asm volatile("ldmatrix.sync.aligned.m8n8.x4.shared.b16 {%0,%1,%2,%3}, [%4];"
                 : "=r"(r0), "=r"(r1), "=r"(r2), "=r"(r3) : "r"(addr));
}
__device__ __forceinline__ void ldmat_x4_t(unsigned& r0, unsigned& r1, unsigned& r2,
                                           unsigned& r3, unsigned addr) {
    asm volatile("ldmatrix.sync.aligned.m8n8.x4.trans.shared.b16 {%0,%1,%2,%3}, [%4];"
                 : "=r"(r0), "=r"(r1), "=r"(r2), "=r"(r3) : "r"(addr));
}
__device__ __forceinline__ void ldmat_x2(unsigned& r0, unsigned& r1, unsigned addr) {
    asm volatile("ldmatrix.sync.aligned.m8n8.x2.shared.b16 {%0,%1}, [%2];"
                 : "=r"(r0), "=r"(r1) : "r"(addr));
}
__device__ __forceinline__ void mma_bf16(float* c, const unsigned* a, const unsigned* b) {
    asm volatile(
        "mma.sync.aligned.m16n8k16.row.col.f32.bf16.bf16.f32 "
        "{%0,%1,%2,%3}, {%4,%5,%6,%7}, {%8,%9}, {%0,%1,%2,%3};"
        : "+f"(c[0]), "+f"(c[1]), "+f"(c[2]), "+f"(c[3])
        : "r"(a[0]), "r"(a[1]), "r"(a[2]), "r"(a[3]), "r"(b[0]), "r"(b[1]));
}
__device__ __forceinline__ void mma_f16(float* c, const unsigned* a, const unsigned* b) {
    asm volatile(
        "mma.sync.aligned.m16n8k16.row.col.f32.f16.f16.f32 "
        "{%0,%1,%2,%3}, {%4,%5,%6,%7}, {%8,%9}, {%0,%1,%2,%3};"
        : "+f"(c[0]), "+f"(c[1]), "+f"(c[2]), "+f"(c[3])
        : "r"(a[0]), "r"(a[1]), "r"(a[2]), "r"(a[3]), "r"(b[0]), "r"(b[1]));
}
__device__ __forceinline__ void cp_async16(unsigned saddr, const void* gaddr) {
    asm volatile("cp.async.cg.shared.global [%0], [%1], 16;" :: "r"(saddr), "l"(gaddr));
}
// pack (x,y) into fp16 hi pair; lo pair returned via 'lo'
__device__ __forceinline__ unsigned pack_hl(float x, float y, unsigned& lo) {
    __half hx = __float2half_rn(x), hy = __float2half_rn(y);
    __half lx = __float2half_rn(x - __half2float(hx));
    __half ly = __float2half_rn(y - __half2float(hy));
    lo = ((unsigned)__half_as_ushort(ly) << 16) | (unsigned)__half_as_ushort(lx);
    return ((unsigned)__half_as_ushort(hy) << 16) | (unsigned)__half_as_ushort(hx);
}

// ---------------- tensor-core GEMM: C[4096,1024] = A @ B^T + bias ----------------
#define PITCH 40
#define KBLK  32
#define MAT_BYTES (128*PITCH*2)
#define STAGE_BYTES (4*MAT_BYTES)
#define GEMM_SMEM (2*STAGE_BYTES)
#define NKB (Edim/KBLK)

template<int DEST>
__global__ __launch_bounds__(256) void gemm_tc(const float* __restrict__ bias,
                                               float* __restrict__ out) {
    extern __shared__ char smc[];
    const unsigned sbase = (unsigned)__cvta_generic_to_shared(smc);
    const int tid = threadIdx.x, lane = tid & 31, wid = tid >> 5;
    const int m0 = blockIdx.y << 7, n0 = blockIdx.x << 7;
    const int wm = (wid & 1) << 6;
    const int wn = (wid >> 1) << 5;

    unsigned soff[8]; const __nv_bfloat16* gp[8];
#pragma unroll
    for (int u = 0; u < 8; u++) {
        const int i = u*256 + tid;
        const int mat = i >> 9;
        const int row = (i >> 2) & 127, c4 = i & 3;
        soff[u] = mat*MAT_BYTES + row*(PITCH*2) + c4*16;
        const __nv_bfloat16* src = (mat==0) ? g_ah : (mat==1) ? g_al
                                  : (mat==2) ? g_bh : g_bl;
        const size_t r = (mat < 2) ? (size_t)(m0 + row) : (size_t)(n0 + row);
        gp[u] = src + r*Edim + c4*8;
    }
    auto load_stage = [&](int kb, int st) {
        const unsigned sb = sbase + st*STAGE_BYTES;
#pragma unroll
        for (int u = 0; u < 8; u++) cp_async16(sb + soff[u], gp[u] + kb*KBLK);
        asm volatile("cp.async.commit_group;");
    };

    float c[4][4][4] = {};
    load_stage(0, 0);

    for (int kb = 0; kb < NKB; kb++) {
        const int st = kb & 1;
        if (kb + 1 < NKB) {
            load_stage(kb + 1, st ^ 1);
            asm volatile("cp.async.wait_group 1;");
        } else {
            asm volatile("cp.async.wait_group 0;");
        }
        __syncthreads();

        const unsigned sAh = sbase + st*STAGE_BYTES;
        const unsigned sAl = sAh + MAT_BYTES;
        const unsigned sBh = sAh + 2*MAT_BYTES;
        const unsigned sBl = sAh + 3*MAT_BYTES;
        const int arow = wm + (lane & 15);
        const int akof = (lane >> 4) << 3;
        const int brow = wn + (lane & 7);
        const int bkof = ((lane >> 3) & 1) << 3;

#pragma unroll
        for (int ks = 0; ks < 2; ks++) {
            const int k0 = ks << 4;
            unsigned ah[4][4], al[4][4], b[4][2];
#pragma unroll
            for (int mf = 0; mf < 4; mf++) {
                const unsigned off = (unsigned)(arow + mf*16)*(PITCH*2) + (k0 + akof)*2;
                ldmat_x4(ah[mf][0], ah[mf][1], ah[mf][2], ah[mf][3], sAh + off);
                ldmat_x4(al[mf][0], al[mf][1], al[mf][2], al[mf][3], sAl + off);
            }
#pragma unroll
            for (int nf = 0; nf < 4; nf++) {
                const unsigned off = (unsigned)(brow + nf*8)*(PITCH*2) + (k0 + bkof)*2;
                ldmat_x2(b[nf][0], b[nf][1], sBh + off);
            }
#pragma unroll
            for (int mf = 0; mf < 4; mf++)
#pragma unroll
                for (int nf = 0; nf < 4; nf++) {
                    mma_bf16(c[mf][nf], ah[mf], b[nf]);
                    mma_bf16(c[mf][nf], al[mf], b[nf]);
                }
#pragma unroll
            for (int nf = 0; nf < 4; nf++) {
                const unsigned off = (unsigned)(brow + nf*8)*(PITCH*2) + (k0 + bkof)*2;
                ldmat_x2(b[nf][0], b[nf][1], sBl + off);
            }
#pragma unroll
            for (int mf = 0; mf < 4; mf++)
#pragma unroll
                for (int nf = 0; nf < 4; nf++)
                    mma_bf16(c[mf][nf], ah[mf], b[nf]);
        }
        __syncthreads();
    }

    // epilogue: bias add; DEST 0/1/2 -> fp16 (hi,lo) head-major; DEST 3 -> fp32 out
    const int g = lane >> 2, tig = lane & 3;
#pragma unroll
    for (int mf = 0; mf < 4; mf++) {
#pragma unroll
        for (int nf = 0; nf < 4; nf++) {
            const int col = n0 + wn + nf*8 + tig*2;
            const float2 bb = *(const float2*)(bias + col);
#pragma unroll
            for (int half = 0; half < 2; half++) {
                const int m = m0 + wm + mf*16 + g + half*8;
                float2 o;
                o.x = c[mf][nf][half*2+0] + bb.x;
                o.y = c[mf][nf][half*2+1] + bb.y;
                if (DEST == 3) {
                    *(float2*)(out + (size_t)m * Edim + col) = o;
                } else {
                    const int s = m >> 1, b2 = m & 1;   // m = s*B + b
                    const int hh = col >> 6, d2 = col & 63;
                    const size_t idx = ((size_t)(b2*Hn + hh) * Sdim + s) * HDdim + d2;
                    unsigned lo;
                    const unsigned hi = pack_hl(o.x, o.y, lo);
                    __half* dh = (DEST == 0) ? g_Qh : (DEST == 1) ? g_Kh : g_Vh;
                    __half* dl = (DEST == 0) ? g_Ql : (DEST == 1) ? g_Kl : g_Vl;
                    *(unsigned*)(dh + idx) = hi;
                    *(unsigned*)(dl + idx) = lo;
                }
            }
        }
    }
}

// ---------------- tensor-core flash attention ----------------
// BLOCK_M=128 (8 warps x m16), BLOCK_N=64 keys/tile, HD=64.
// QK = QhKh + QhKl + QlKh; PV = PhVh + PhVl + PlVh (fp16 split, fp32 accum).
#define FPITCH_B 144                    // 72 halves per row
#define QSM_BYTES (2*128*FPITCH_B)      // 36864
#define KSTAGE_BYTES (4*64*FPITCH_B)    // 36864 (Kh,Kl,Vh,Vl)
#define FL_SMEM (QSM_BYTES + 2*KSTAGE_BYTES)   // 110592

__global__ __launch_bounds__(256) void flash_tc() {
    extern __shared__ char smc[];
    const unsigned sbase = (unsigned)__cvta_generic_to_shared(smc);
    const unsigned sQ = sbase;
    const unsigned sKst = sbase + QSM_BYTES;
    const int tid = threadIdx.x, lane = tid & 31, wid = tid >> 5;
    const int bh = blockIdx.y;
    const int q0 = blockIdx.x << 7;
    const int wm = wid << 4;

    const size_t qbase = ((size_t)bh * Sdim + q0) * HDdim;
    const size_t kbase = (size_t)bh * Sdim * HDdim;

    // Q tile (128x64 fp16 hi+lo) via cp.async
#pragma unroll
    for (int u = 0; u < 8; u++) {
        const int i = u*256 + tid;
        const int mat = i >> 10, row = (i >> 3) & 127, c8 = i & 7;
        const __half* src = (mat ? g_Ql : g_Qh) + qbase + (size_t)row*HDdim + c8*8;
        cp_async16(sQ + mat*(128*FPITCH_B) + row*FPITCH_B + c8*16, src);
    }
    auto load_kv = [&](int kt, int st) {
        const unsigned sb = sKst + st*KSTAGE_BYTES;
#pragma unroll
        for (int u = 0; u < 8; u++) {
            const int i = u*256 + tid;
            const int mat = i >> 9, row = (i >> 3) & 63, c8 = i & 7;
            const __half* src = (mat==0 ? g_Kh : mat==1 ? g_Kl : mat==2 ? g_Vh : g_Vl)
                              + kbase + (size_t)(kt*64 + row)*HDdim + c8*8;
            cp_async16(sb + mat*(64*FPITCH_B) + row*FPITCH_B + c8*16, src);
        }
        asm volatile("cp.async.commit_group;");
    };
    load_kv(0, 0);   // Q chunks + stage0 -> one group

    asm volatile("cp.async.wait_group 0;");
    __syncthreads();

    // Q A-fragments, loaded once
    unsigned qh[4][4], ql[4][4];
    {
        const unsigned aoff = (unsigned)(wm + (lane & 15))*FPITCH_B + ((lane >> 4) << 3)*2;
#pragma unroll
        for (int kf = 0; kf < 4; kf++) {
            ldmat_x4(qh[kf][0], qh[kf][1], qh[kf][2], qh[kf][3], sQ + aoff + kf*32);
            ldmat_x4(ql[kf][0], ql[kf][1], ql[kf][2], ql[kf][3],
                     sQ + 128*FPITCH_B + aoff + kf*32);
        }
    }

    float acc[8][4] = {};
    float mr0 = -1e30f, mr1 = -1e30f, lr0 = 0.f, lr1 = 0.f;

    for (int kt = 0; kt < Sdim/64; kt++) {
        const int st = kt & 1;
        if (kt) {
            asm volatile("cp.async.wait_group 0;");
            __syncthreads();
        }
        if (kt + 1 < Sdim/64) load_kv(kt + 1, st ^ 1);

        const unsigned kb = sKst + st*KSTAGE_BYTES;

        // ---- S = Q @ K^T ----
        float s[8][4] = {};
        {
            const int krow = ((lane >> 4) & 1)*8 + (lane & 7);
            const int ksel = ((lane >> 3) & 1)*8;
#pragma unroll
            for (int kf = 0; kf < 4; kf++) {
                unsigned bhf[4][4], blf[4][4];
                const unsigned coff = (unsigned)(kf*16 + ksel)*2;
#pragma unroll
                for (int np = 0; np < 4; np++) {
                    const unsigned ad = kb + (unsigned)(np*16 + krow)*FPITCH_B + coff;
                    ldmat_x4(bhf[np][0], bhf[np][1], bhf[np][2], bhf[np][3], ad);
                    ldmat_x4(blf[np][0], blf[np][1], blf[np][2], blf[np][3],
                             ad + 64*FPITCH_B);
                }
#pragma unroll
                for (int np = 0; np < 4; np++) {
                    mma_f16(s[2*np],   qh[kf], &bhf[np][0]);
                    mma_f16(s[2*np+1], qh[kf], &bhf[np][2]);
                    mma_f16(s[2*np],   qh[kf], &blf[np][0]);
                    mma_f16(s[2*np+1], qh[kf], &blf[np][2]);
                    mma_f16(s[2*np],   ql[kf], &bhf[np][0]);
                    mma_f16(s[2*np+1], ql[kf], &bhf[np][2]);
                }
            }
        }

        // ---- online softmax (rows g, g+8; quad shfl reduce) ----
#pragma unroll
        for (int rh = 0; rh < 2; rh++) {
            const int i0 = rh*2;
            float mx = fmaxf(s[0][i0], s[0][i0+1]);
#pragma unroll
            for (int nf = 1; nf < 8; nf++)
                mx = fmaxf(mx, fmaxf(s[nf][i0], s[nf][i0+1]));
            mx = fmaxf(mx, __shfl_xor_sync(0xffffffffu, mx, 1));
            mx = fmaxf(mx, __shfl_xor_sync(0xffffffffu, mx, 2));
            const float mold = rh ? mr1 : mr0;
            const float mnew = fmaxf(mold, mx);
            const float alpha = __expf(mold - mnew);
            float rs = 0.f;
#pragma unroll
            for (int nf = 0; nf < 8; nf++) {
                s[nf][i0]   = __expf(s[nf][i0]   - mnew);
                s[nf][i0+1] = __expf(s[nf][i0+1] - mnew);
                rs += s[nf][i0] + s[nf][i0+1];
            }
            rs += __shfl_xor_sync(0xffffffffu, rs, 1);
            rs += __shfl_xor_sync(0xffffffffu, rs, 2);
            if (rh) { lr1 = lr1*alpha + rs; mr1 = mnew; }
            else    { lr0 = lr0*alpha + rs; mr0 = mnew; }
#pragma unroll
            for (int nf = 0; nf < 8; nf++) {
                acc[nf][i0]   *= alpha;
                acc[nf][i0+1] *= alpha;
            }
        }

        // ---- P -> fp16 split A-fragments (C layout == A layout) ----
        unsigned pa[4][4], pl[4][4];
#pragma unroll
        for (int kf = 0; kf < 4; kf++) {
            pa[kf][0] = pack_hl(s[2*kf][0],   s[2*kf][1],   pl[kf][0]);
            pa[kf][1] = pack_hl(s[2*kf][2],   s[2*kf][3],   pl[kf][1]);
            pa[kf][2] = pack_hl(s[2*kf+1][0], s[2*kf+1][1], pl[kf][2]);
            pa[kf][3] = pack_hl(s[2*kf+1][2], s[2*kf+1][3], pl[kf][3]);
        }

        // ---- O += P @ V (V via ldmatrix.trans) ----
        {
            const int vrow = lane & 15;
            const int vsel = ((lane >> 4) & 1)*8;
#pragma unroll
            for (int kf = 0; kf < 4; kf++) {
                unsigned vhf[4][4], vlf[4][4];
#pragma unroll
                for (int np = 0; np < 4; np++) {
                    const unsigned ad = kb + 2*(64*FPITCH_B)
                        + (unsigned)(kf*16 + vrow)*FPITCH_B + (np*16 + vsel)*2;
                    ldmat_x4_t(vhf[np][0], vhf[np][1], vhf[np][2], vhf[np][3], ad);
                    ldmat_x4_t(vlf[np][0], vlf[np][1], vlf[np][2], vlf[np][3],
                               ad + 64*FPITCH_B);
                }
#pragma unroll
                for (int np = 0; np < 4; np++) {
                    mma_f16(acc[2*np],   pa[kf], &vhf[np][0]);
                    mma_f16(acc[2*np+1], pa[kf], &vhf[np][2]);
                    mma_f16(acc[2*np],   pa[kf], &vlf[np][0]);
                    mma_f16(acc[2*np+1], pa[kf], &vlf[np][2]);
                    mma_f16(acc[2*np],   pl[kf], &vhf[np][0]);
                    mma_f16(acc[2*np+1], pl[kf], &vhf[np][2]);
                }
            }
        }
    }

    // epilogue -> g_ctx fp32 [s*B+b][E]
    const int b = bh >> 4, hh = bh & 15;
    const int g = lane >> 2, tig = lane & 3;
    const float inv0 = 1.0f / lr0, inv1 = 1.0f / lr1;
    const int sg = q0 + wm + g;
#pragma unroll
    for (int nf = 0; nf < 8; nf++) {
        const int d = nf*8 + tig*2;
        float2 o0 = { acc[nf][0]*inv0, acc[nf][1]*inv0 };
        float2 o1 = { acc[nf][2]*inv1, acc[nf][3]*inv1 };
        *(float2*)(g_ctx + ((size_t)sg*Bdim + b)*Edim + hh*HDdim + d) = o0;
        *(float2*)(g_ctx + ((size_t)(sg+8)*Bdim + b)*Edim + hh*HDdim + d) = o1;
    }
}

// ---------------- launch ----------------
extern "C" void kernel_launch(void* const* d_in, const int* in_sizes, int n_in,
                              void* d_out, int out_size) {
    const float* query = (const float*)d_in[0];
    const float* key_  = (const float*)d_in[1];
    const float* value = (const float*)d_in[2];
    const float* Wq = (const float*)d_in[3];
    const float* bq = (const float*)d_in[4];
    const float* Wk = (const float*)d_in[5];
    const float* bk = (const float*)d_in[6];
    const float* Wv = (const float*)d_in[7];
    const float* bv = (const float*)d_in[8];
    const float* Wo = (const float*)d_in[9];
    const float* bo = (const float*)d_in[10];
    float* out = (float*)d_out;

    static bool attr_set = false;
    if (!attr_set) {
        cudaFuncSetAttribute(flash_tc, cudaFuncAttributeMaxDynamicSharedMemorySize, FL_SMEM);
        cudaFuncSetAttribute(gemm_tc<0>, cudaFuncAttributeMaxDynamicSharedMemorySize, GEMM_SMEM);
        cudaFuncSetAttribute(gemm_tc<1>, cudaFuncAttributeMaxDynamicSharedMemorySize, GEMM_SMEM);
        cudaFuncSetAttribute(gemm_tc<2>, cudaFuncAttributeMaxDynamicSharedMemorySize, GEMM_SMEM);
        cudaFuncSetAttribute(gemm_tc<3>, cudaFuncAttributeMaxDynamicSharedMemorySize, GEMM_SMEM);
        attr_set = true;
    }

    const int NA = Mrows * Edim;   // 4M
    const int NB = Edim * Edim;    // 1M
    const dim3 ggemm(Edim/128, Mrows/128);   // 8 x 32

    split_kernel<0><<<NA/1024, 256>>>(query, NA);
    split_kernel<1><<<NB/1024, 256>>>(Wq, NB);
    gemm_tc<0><<<ggemm, 256, GEMM_SMEM>>>(bq, nullptr);

    split_kernel<0><<<NA/1024, 256>>>(key_, NA);
    split_kernel<1><<<NB/1024, 256>>>(Wk, NB);
    gemm_tc<1><<<ggemm, 256, GEMM_SMEM>>>(bk, nullptr);

    split_kernel<0><<<NA/1024, 256>>>(value, NA);
    split_kernel<1><<<NB/1024, 256>>>(Wv, NB);
    gemm_tc<2><<<ggemm, 256, GEMM_SMEM>>>(bv, nullptr);

    flash_tc<<<dim3(Sdim/128, Bdim*Hn), 256, FL_SMEM>>>();

    split_kernel<0><<<NA/1024, 256>>>(nullptr, NA);   // ctx
    split_kernel<1><<<NB/1024, 256>>>(Wo, NB);
    gemm_tc<3><<<ggemm, 256, GEMM_SMEM>>>(bo, out);
}

// round 7
// speedup vs baseline: 3.0922x; 1.0027x over previous
#include <cuda_runtime.h>
#include <cuda_bf16.h>
#include <cuda_fp16.h>

#define Sdim 2048
#define Bdim 2
#define Edim 1024
#define Hn   16
#define HDdim 64
#define Mrows (Sdim*Bdim)   // 4096 token rows

// ---------------- scratch (device globals: allocation-free) ----------------
__device__ float g_ctx[(size_t)Mrows*Edim];         // [s*B+b][E]

// fp16 split QKV (written by projection epilogues), layout [b*H+h][s][d]
#define QKV_ELEMS ((size_t)Bdim*Hn*Sdim*HDdim)
__device__ __align__(16) __half g_Qh[QKV_ELEMS];
__device__ __align__(16) __half g_Ql[QKV_ELEMS];
__device__ __align__(16) __half g_Kh[QKV_ELEMS];
__device__ __align__(16) __half g_Kl[QKV_ELEMS];
__device__ __align__(16) __half g_Vh[QKV_ELEMS];
__device__ __align__(16) __half g_Vl[QKV_ELEMS];

// bf16 split scratch for projection GEMMs
__device__ __align__(16) __nv_bfloat16 g_ah[(size_t)Mrows*Edim];
__device__ __align__(16) __nv_bfloat16 g_al[(size_t)Mrows*Edim];
__device__ __align__(16) __nv_bfloat16 g_bh[(size_t)Edim*Edim];
__device__ __align__(16) __nv_bfloat16 g_bl[(size_t)Edim*Edim];

// ---------------- split fp32 -> (hi, lo) bf16 ----------------
__device__ __forceinline__ void split1(float x, __nv_bfloat16& h, __nv_bfloat16& l) {
    h = __float2bfloat16(x);
    l = __float2bfloat16(x - __bfloat162float(h));
}
template<int DST>
__global__ __launch_bounds__(256) void split_kernel(const float* __restrict__ xin, int n) {
    const float* x = xin ? xin : (const float*)g_ctx;
    __nv_bfloat16* hi = (DST == 0) ? g_ah : g_bh;
    __nv_bfloat16* lo = (DST == 0) ? g_al : g_bl;
    int i = (blockIdx.x * blockDim.x + threadIdx.x) * 4;
    if (i < n) {
        float4 v = *(const float4*)(x + i);
        __nv_bfloat16 h0,h1,h2,h3,l0,l1,l2,l3;
        split1(v.x,h0,l0); split1(v.y,h1,l1); split1(v.z,h2,l2); split1(v.w,h3,l3);
        __nv_bfloat162* ph = (__nv_bfloat162*)(hi + i);
        ph[0] = __halves2bfloat162(h0,h1); ph[1] = __halves2bfloat162(h2,h3);
        __nv_bfloat162* pl = (__nv_bfloat162*)(lo + i);
        pl[0] = __halves2bfloat162(l0,l1); pl[1] = __halves2bfloat162(l2,l3);
    }
}

// ---------------- mma helpers ----------------
__device__ __forceinline__ void ldmat_x4(unsigned& r0, unsigned& r1, unsigned& r2,
                                         unsigned& r3, unsigned addr) {
    asm volatile("ldmatrix.sync.aligned.m8n8.x4.shared.b16 {%0,%1,%2,%3}, [%4];"
                 : "=r"(r0), "=r"(r1), "=r"(r2), "=r"(r3) : "r"(addr));
}
__device__ __forceinline__ void ldmat_x4_t(unsigned& r0, unsigned& r1, unsigned& r2,
                                           unsigned& r3, unsigned addr) {
    asm volatile("ldmatrix.sync.aligned.m8n8.x4.trans.shared.b16 {%0,%1,%2,%3}, [%4];"
                 : "=r"(r0), "=r"(r1), "=r"(r2), "=r"(r3) : "r"(addr));
}
__device__ __forceinline__ void ldmat_x2(unsigned& r0, unsigned& r1, unsigned addr) {
    asm volatile("ldmatrix.sync.aligned.m8n8.x2.shared.b16 {%0,%1}, [%2];"
                 : "=r"(r0), "=r"(r1) : "r"(addr));
}
__device__ __forceinline__ void mma_bf16(float* c, const unsigned* a, const unsigned* b) {
    asm volatile(
        "mma.sync.aligned.m16n8k16.row.col.f32.bf16.bf16.f32 "
        "{%0,%1,%2,%3}, {%4,%5,%6,%7}, {%8,%9}, {%0,%1,%2,%3};"
        : "+f"(c[0]), "+f"(c[1]), "+f"(c[2]), "+f"(c[3])
        : "r"(a[0]), "r"(a[1]), "r"(a[2]), "r"(a[3]), "r"(b[0]), "r"(b[1]));
}
__device__ __forceinline__ void mma_f16(float* c, const unsigned* a, const unsigned* b) {
    asm volatile(
        "mma.sync.aligned.m16n8k16.row.col.f32.f16.f16.f32 "
        "{%0,%1,%2,%3}, {%4,%5,%6,%7}, {%8,%9}, {%0,%1,%2,%3};"
        : "+f"(c[0]), "+f"(c[1]), "+f"(c[2]), "+f"(c[3])
        : "r"(a[0]), "r"(a[1]), "r"(a[2]), "r"(a[3]), "r"(b[0]), "r"(b[1]));
}
__device__ __forceinline__ void cp_async16(unsigned saddr, const void* gaddr) {
    asm volatile("cp.async.cg.shared.global [%0], [%1], 16;" :: "r"(saddr), "l"(gaddr));
}
// pack (x,y) into fp16 hi pair; lo pair returned via 'lo'
__device__ __forceinline__ unsigned pack_hl(float x, float y, unsigned& lo) {
    __half hx = __float2half_rn(x), hy = __float2half_rn(y);
    __half lx = __float2half_rn(x - __half2float(hx));
    __half ly = __float2half_rn(y - __half2float(hy));
    lo = ((unsigned)__half_as_ushort(ly) << 16) | (unsigned)__half_as_ushort(lx);
    return ((unsigned)__half_as_ushort(hy) << 16) | (unsigned)__half_as_ushort(hx);
}

// ---------------- tensor-core GEMM: C[4096,1024] = A @ B^T + bias ----------------
#define PITCH 40
#define KBLK  32
#define MAT_BYTES (128*PITCH*2)
#define STAGE_BYTES (4*MAT_BYTES)
#define GEMM_SMEM (2*STAGE_BYTES)
#define NKB (Edim/KBLK)

template<int DEST>
__global__ __launch_bounds__(256) void gemm_tc(const float* __restrict__ bias,
                                               float* __restrict__ out) {
    extern __shared__ char smc[];
    const unsigned sbase = (unsigned)__cvta_generic_to_shared(smc);
    const int tid = threadIdx.x, lane = tid & 31, wid = tid >> 5;
    const int m0 = blockIdx.y << 7, n0 = blockIdx.x << 7;
    const int wm = (wid & 1) << 6;
    const int wn = (wid >> 1) << 5;

    unsigned soff[8]; const __nv_bfloat16* gp[8];
#pragma unroll
    for (int u = 0; u < 8; u++) {
        const int i = u*256 + tid;
        const int mat = i >> 9;
        const int row = (i >> 2) & 127, c4 = i & 3;
        soff[u] = mat*MAT_BYTES + row*(PITCH*2) + c4*16;
        const __nv_bfloat16* src = (mat==0) ? g_ah : (mat==1) ? g_al
                                  : (mat==2) ? g_bh : g_bl;
        const size_t r = (mat < 2) ? (size_t)(m0 + row) : (size_t)(n0 + row);
        gp[u] = src + r*Edim + c4*8;
    }
    auto load_stage = [&](int kb, int st) {
        const unsigned sb = sbase + st*STAGE_BYTES;
#pragma unroll
        for (int u = 0; u < 8; u++) cp_async16(sb + soff[u], gp[u] + kb*KBLK);
        asm volatile("cp.async.commit_group;");
    };

    float c[4][4][4] = {};
    load_stage(0, 0);

    for (int kb = 0; kb < NKB; kb++) {
        const int st = kb & 1;
        if (kb + 1 < NKB) {
            load_stage(kb + 1, st ^ 1);
            asm volatile("cp.async.wait_group 1;");
        } else {
            asm volatile("cp.async.wait_group 0;");
        }
        __syncthreads();

        const unsigned sAh = sbase + st*STAGE_BYTES;
        const unsigned sAl = sAh + MAT_BYTES;
        const unsigned sBh = sAh + 2*MAT_BYTES;
        const unsigned sBl = sAh + 3*MAT_BYTES;
        const int arow = wm + (lane & 15);
        const int akof = (lane >> 4) << 3;
        const int brow = wn + (lane & 7);
        const int bkof = ((lane >> 3) & 1) << 3;

#pragma unroll
        for (int ks = 0; ks < 2; ks++) {
            const int k0 = ks << 4;
            unsigned ah[4][4], al[4][4], b[4][2];
#pragma unroll
            for (int mf = 0; mf < 4; mf++) {
                const unsigned off = (unsigned)(arow + mf*16)*(PITCH*2) + (k0 + akof)*2;
                ldmat_x4(ah[mf][0], ah[mf][1], ah[mf][2], ah[mf][3], sAh + off);
                ldmat_x4(al[mf][0], al[mf][1], al[mf][2], al[mf][3], sAl + off);
            }
#pragma unroll
            for (int nf = 0; nf < 4; nf++) {
                const unsigned off = (unsigned)(brow + nf*8)*(PITCH*2) + (k0 + bkof)*2;
                ldmat_x2(b[nf][0], b[nf][1], sBh + off);
            }
#pragma unroll
            for (int mf = 0; mf < 4; mf++)
#pragma unroll
                for (int nf = 0; nf < 4; nf++) {
                    mma_bf16(c[mf][nf], ah[mf], b[nf]);
                    mma_bf16(c[mf][nf], al[mf], b[nf]);
                }
#pragma unroll
            for (int nf = 0; nf < 4; nf++) {
                const unsigned off = (unsigned)(brow + nf*8)*(PITCH*2) + (k0 + bkof)*2;
                ldmat_x2(b[nf][0], b[nf][1], sBl + off);
            }
#pragma unroll
            for (int mf = 0; mf < 4; mf++)
#pragma unroll
                for (int nf = 0; nf < 4; nf++)
                    mma_bf16(c[mf][nf], ah[mf], b[nf]);
        }
        __syncthreads();
    }

    // epilogue: bias add; DEST 0/1/2 -> fp16 (hi,lo) head-major; DEST 3 -> fp32 out
    const int g = lane >> 2, tig = lane & 3;
#pragma unroll
    for (int mf = 0; mf < 4; mf++) {
#pragma unroll
        for (int nf = 0; nf < 4; nf++) {
            const int col = n0 + wn + nf*8 + tig*2;
            const float2 bb = *(const float2*)(bias + col);
#pragma unroll
            for (int half = 0; half < 2; half++) {
                const int m = m0 + wm + mf*16 + g + half*8;
                float2 o;
                o.x = c[mf][nf][half*2+0] + bb.x;
                o.y = c[mf][nf][half*2+1] + bb.y;
                if (DEST == 3) {
                    *(float2*)(out + (size_t)m * Edim + col) = o;
                } else {
                    const int s = m >> 1, b2 = m & 1;   // m = s*B + b
                    const int hh = col >> 6, d2 = col & 63;
                    const size_t idx = ((size_t)(b2*Hn + hh) * Sdim + s) * HDdim + d2;
                    unsigned lo;
                    const unsigned hi = pack_hl(o.x, o.y, lo);
                    __half* dh = (DEST == 0) ? g_Qh : (DEST == 1) ? g_Kh : g_Vh;
                    __half* dl = (DEST == 0) ? g_Ql : (DEST == 1) ? g_Kl : g_Vl;
                    *(unsigned*)(dh + idx) = hi;
                    *(unsigned*)(dl + idx) = lo;
                }
            }
        }
    }
}

// ---------------- tensor-core flash attention ----------------
// BLOCK_M=128 (8 warps x m16), BLOCK_N=64 keys/tile, HD=64.
// QK = QhKh + QhKl + QlKh; PV = PhVh + PhVl + PlVh (fp16 split, fp32 accum).
#define FPITCH_B 144                    // 72 halves per row
#define QSM_BYTES (2*128*FPITCH_B)      // 36864
#define KSTAGE_BYTES (4*64*FPITCH_B)    // 36864 (Kh,Kl,Vh,Vl)
#define FL_SMEM (QSM_BYTES + 2*KSTAGE_BYTES)   // 110592

__global__ __launch_bounds__(256) void flash_tc() {
    extern __shared__ char smc[];
    const unsigned sbase = (unsigned)__cvta_generic_to_shared(smc);
    const unsigned sQ = sbase;
    const unsigned sKst = sbase + QSM_BYTES;
    const int tid = threadIdx.x, lane = tid & 31, wid = tid >> 5;
    const int bh = blockIdx.y;
    const int q0 = blockIdx.x << 7;
    const int wm = wid << 4;

    const size_t qbase = ((size_t)bh * Sdim + q0) * HDdim;
    const size_t kbase = (size_t)bh * Sdim * HDdim;

    // Q tile (128x64 fp16 hi+lo) via cp.async
#pragma unroll
    for (int u = 0; u < 8; u++) {
        const int i = u*256 + tid;
        const int mat = i >> 10, row = (i >> 3) & 127, c8 = i & 7;
        const __half* src = (mat ? g_Ql : g_Qh) + qbase + (size_t)row*HDdim + c8*8;
        cp_async16(sQ + mat*(128*FPITCH_B) + row*FPITCH_B + c8*16, src);
    }
    auto load_kv = [&](int kt, int st) {
        const unsigned sb = sKst + st*KSTAGE_BYTES;
#pragma unroll
        for (int u = 0; u < 8; u++) {
            const int i = u*256 + tid;
            const int mat = i >> 9, row = (i >> 3) & 63, c8 = i & 7;
            const __half* src = (mat==0 ? g_Kh : mat==1 ? g_Kl : mat==2 ? g_Vh : g_Vl)
                              + kbase + (size_t)(kt*64 + row)*HDdim + c8*8;
            cp_async16(sb + mat*(64*FPITCH_B) + row*FPITCH_B + c8*16, src);
        }
        asm volatile("cp.async.commit_group;");
    };
    load_kv(0, 0);   // Q chunks + stage0 -> one group

    asm volatile("cp.async.wait_group 0;");
    __syncthreads();

    // Q A-fragments, loaded once
    unsigned qh[4][4], ql[4][4];
    {
        const unsigned aoff = (unsigned)(wm + (lane & 15))*FPITCH_B + ((lane >> 4) << 3)*2;
#pragma unroll
        for (int kf = 0; kf < 4; kf++) {
            ldmat_x4(qh[kf][0], qh[kf][1], qh[kf][2], qh[kf][3], sQ + aoff + kf*32);
            ldmat_x4(ql[kf][0], ql[kf][1], ql[kf][2], ql[kf][3],
                     sQ + 128*FPITCH_B + aoff + kf*32);
        }
    }

    float acc[8][4] = {};
    float mr0 = -1e30f, mr1 = -1e30f, lr0 = 0.f, lr1 = 0.f;

    for (int kt = 0; kt < Sdim/64; kt++) {
        const int st = kt & 1;
        if (kt) {
            asm volatile("cp.async.wait_group 0;");
            __syncthreads();
        }
        if (kt + 1 < Sdim/64) load_kv(kt + 1, st ^ 1);

        const unsigned kb = sKst + st*KSTAGE_BYTES;

        // ---- S = Q @ K^T ----
        float s[8][4] = {};
        {
            const int krow = ((lane >> 4) & 1)*8 + (lane & 7);
            const int ksel = ((lane >> 3) & 1)*8;
#pragma unroll
            for (int kf = 0; kf < 4; kf++) {
                unsigned bhf[4][4], blf[4][4];
                const unsigned coff = (unsigned)(kf*16 + ksel)*2;
#pragma unroll
                for (int np = 0; np < 4; np++) {
                    const unsigned ad = kb + (unsigned)(np*16 + krow)*FPITCH_B + coff;
                    ldmat_x4(bhf[np][0], bhf[np][1], bhf[np][2], bhf[np][3], ad);
                    ldmat_x4(blf[np][0], blf[np][1], blf[np][2], blf[np][3],
                             ad + 64*FPITCH_B);
                }
#pragma unroll
                for (int np = 0; np < 4; np++) {
                    mma_f16(s[2*np],   qh[kf], &bhf[np][0]);
                    mma_f16(s[2*np+1], qh[kf], &bhf[np][2]);
                    mma_f16(s[2*np],   qh[kf], &blf[np][0]);
                    mma_f16(s[2*np+1], qh[kf], &blf[np][2]);
                    mma_f16(s[2*np],   ql[kf], &bhf[np][0]);
                    mma_f16(s[2*np+1], ql[kf], &bhf[np][2]);
                }
            }
        }

        // ---- online softmax (rows g, g+8; quad shfl reduce) ----
#pragma unroll
        for (int rh = 0; rh < 2; rh++) {
            const int i0 = rh*2;
            float mx = fmaxf(s[0][i0], s[0][i0+1]);
#pragma unroll
            for (int nf = 1; nf < 8; nf++)
                mx = fmaxf(mx, fmaxf(s[nf][i0], s[nf][i0+1]));
            mx = fmaxf(mx, __shfl_xor_sync(0xffffffffu, mx, 1));
            mx = fmaxf(mx, __shfl_xor_sync(0xffffffffu, mx, 2));
            const float mold = rh ? mr1 : mr0;
            const float mnew = fmaxf(mold, mx);
            const float alpha = __expf(mold - mnew);
            float rs = 0.f;
#pragma unroll
            for (int nf = 0; nf < 8; nf++) {
                s[nf][i0]   = __expf(s[nf][i0]   - mnew);
                s[nf][i0+1] = __expf(s[nf][i0+1] - mnew);
                rs += s[nf][i0] + s[nf][i0+1];
            }
            rs += __shfl_xor_sync(0xffffffffu, rs, 1);
            rs += __shfl_xor_sync(0xffffffffu, rs, 2);
            if (rh) { lr1 = lr1*alpha + rs; mr1 = mnew; }
            else    { lr0 = lr0*alpha + rs; mr0 = mnew; }
#pragma unroll
            for (int nf = 0; nf < 8; nf++) {
                acc[nf][i0]   *= alpha;
                acc[nf][i0+1] *= alpha;
            }
        }

        // ---- P -> fp16 split A-fragments (C layout == A layout) ----
        unsigned pa[4][4], pl[4][4];
#pragma unroll
        for (int kf = 0; kf < 4; kf++) {
            pa[kf][0] = pack_hl(s[2*kf][0],   s[2*kf][1],   pl[kf][0]);
            pa[kf][1] = pack_hl(s[2*kf][2],   s[2*kf][3],   pl[kf][1]);
            pa[kf][2] = pack_hl(s[2*kf+1][0], s[2*kf+1][1], pl[kf][2]);
            pa[kf][3] = pack_hl(s[2*kf+1][2], s[2*kf+1][3], pl[kf][3]);
        }

        // ---- O += P @ V (V via ldmatrix.trans) ----
        {
            const int vrow = lane & 15;
            const int vsel = ((lane >> 4) & 1)*8;
#pragma unroll
            for (int kf = 0; kf < 4; kf++) {
                unsigned vhf[4][4], vlf[4][4];
#pragma unroll
                for (int np = 0; np < 4; np++) {
                    const unsigned ad = kb + 2*(64*FPITCH_B)
                        + (unsigned)(kf*16 + vrow)*FPITCH_B + (np*16 + vsel)*2;
                    ldmat_x4_t(vhf[np][0], vhf[np][1], vhf[np][2], vhf[np][3], ad);
                    ldmat_x4_t(vlf[np][0], vlf[np][1], vlf[np][2], vlf[np][3],
                               ad + 64*FPITCH_B);
                }
#pragma unroll
                for (int np = 0; np < 4; np++) {
                    mma_f16(acc[2*np],   pa[kf], &vhf[np][0]);
                    mma_f16(acc[2*np+1], pa[kf], &vhf[np][2]);
                    mma_f16(acc[2*np],   pa[kf], &vlf[np][0]);
                    mma_f16(acc[2*np+1], pa[kf], &vlf[np][2]);
                    mma_f16(acc[2*np],   pl[kf], &vhf[np][0]);
                    mma_f16(acc[2*np+1], pl[kf], &vhf[np][2]);
                }
            }
        }
    }

    // epilogue -> g_ctx fp32 [s*B+b][E]
    const int b = bh >> 4, hh = bh & 15;
    const int g = lane >> 2, tig = lane & 3;
    const float inv0 = 1.0f / lr0, inv1 = 1.0f / lr1;
    const int sg = q0 + wm + g;
#pragma unroll
    for (int nf = 0; nf < 8; nf++) {
        const int d = nf*8 + tig*2;
        float2 o0 = { acc[nf][0]*inv0, acc[nf][1]*inv0 };
        float2 o1 = { acc[nf][2]*inv1, acc[nf][3]*inv1 };
        *(float2*)(g_ctx + ((size_t)sg*Bdim + b)*Edim + hh*HDdim + d) = o0;
        *(float2*)(g_ctx + ((size_t)(sg+8)*Bdim + b)*Edim + hh*HDdim + d) = o1;
    }
}

// ---------------- launch ----------------
extern "C" void kernel_launch(void* const* d_in, const int* in_sizes, int n_in,
                              void* d_out, int out_size) {
    const float* query = (const float*)d_in[0];
    const float* key_  = (const float*)d_in[1];
    const float* value = (const float*)d_in[2];
    const float* Wq = (const float*)d_in[3];
    const float* bq = (const float*)d_in[4];
    const float* Wk = (const float*)d_in[5];
    const float* bk = (const float*)d_in[6];
    const float* Wv = (const float*)d_in[7];
    const float* bv = (const float*)d_in[8];
    const float* Wo = (const float*)d_in[9];
    const float* bo = (const float*)d_in[10];
    float* out = (float*)d_out;

    static bool attr_set = false;
    if (!attr_set) {
        cudaFuncSetAttribute(flash_tc, cudaFuncAttributeMaxDynamicSharedMemorySize, FL_SMEM);
        cudaFuncSetAttribute(gemm_tc<0>, cudaFuncAttributeMaxDynamicSharedMemorySize, GEMM_SMEM);
        cudaFuncSetAttribute(gemm_tc<1>, cudaFuncAttributeMaxDynamicSharedMemorySize, GEMM_SMEM);
        cudaFuncSetAttribute(gemm_tc<2>, cudaFuncAttributeMaxDynamicSharedMemorySize, GEMM_SMEM);
        cudaFuncSetAttribute(gemm_tc<3>, cudaFuncAttributeMaxDynamicSharedMemorySize, GEMM_SMEM);
        attr_set = true;
    }

    const int NA = Mrows * Edim;   // 4M
    const int NB = Edim * Edim;    // 1M
    const dim3 ggemm(Edim/128, Mrows/128);   // 8 x 32

    split_kernel<0><<<NA/1024, 256>>>(query, NA);
    split_kernel<1><<<NB/1024, 256>>>(Wq, NB);
    gemm_tc<0><<<ggemm, 256, GEMM_SMEM>>>(bq, nullptr);

    split_kernel<0><<<NA/1024, 256>>>(key_, NA);
    split_kernel<1><<<NB/1024, 256>>>(Wk, NB);
    gemm_tc<1><<<ggemm, 256, GEMM_SMEM>>>(bk, nullptr);

    split_kernel<0><<<NA/1024, 256>>>(value, NA);
    split_kernel<1><<<NB/1024, 256>>>(Wv, NB);
    gemm_tc<2><<<ggemm, 256, GEMM_SMEM>>>(bv, nullptr);

    flash_tc<<<dim3(Sdim/128, Bdim*Hn), 256, FL_SMEM>>>();

    split_kernel<0><<<NA/1024, 256>>>(nullptr, NA);   // ctx
    split_kernel<1><<<NB/1024, 256>>>(Wo, NB);
    gemm_tc<3><<<ggemm, 256, GEMM_SMEM>>>(bo, out);
}